// round 12
// baseline (speedup 1.0000x reference)
#include <cuda_runtime.h>
#include <cuda_fp16.h>
#include <cstdint>
#include <math.h>

#define FDIM 256
#define NB 8
#define NPATH 20
#define BDIM 8192
#define NROWS (NB * BDIM)          // 65536 GEMM rows (plane-major)
#define KC 32                      // k per pipeline chunk
#define NCHUNK (FDIM / KC)         // 8
#define GBN 64                     // n per CTA (per side; both sides computed)

// smem: per stage A 16KB + B 16KB; 3 stages
#define A_STAGE_B 16384
#define STAGE_B 32768
#define SMEM_TOTAL (3 * STAGE_B)   // 98304

// ---------------- scratch (device globals) ----------------
// A fragment-packed: [plane 8][btile 64][chunk 8][ks 4][m16 8][lane 32][4]
__device__ float g_xt[(size_t)NROWS * FDIM];               // 64MB
// B fragment-packed: [g 4][nt 4][chunk 8][s 2][n8l 8][ks 4][lane 32][2]
__device__ float g_wt[(size_t)4 * 4 * 8 * 4096];           // 2MB
__device__ __half g_Lh[(size_t)FDIM * NROWS];              // 32MB [n][row]
__device__ __half g_Rh[(size_t)FDIM * NROWS];              // 32MB [n][row]
__device__ float g_Wc[FDIM * 64];
__device__ float g_sig[FDIM * 4];

__constant__ int c_masks[8] = {0, 1, 2, 4, 3, 5, 6, 7};
__constant__ int c_plut[64] = {
     0, -1, -1, -1,   -1,  1, -1, -1,   -1, -1,  2, -1,   -1, -1, -1,  3,
    -1,  4, -1, -1,    5, -1,  6, -1,   -1,  7, -1,  8,   -1, -1,  9, -1,
    -1, -1, 10, -1,   -1, 11, -1, 12,   13, -1, 14, -1,   -1, 15, -1, -1,
    -1, -1, -1, 16,   -1, -1, 17, -1,   -1, 18, -1, -1,   19, -1, -1, -1
};
__constant__ int c_grade_of_plane[8] = {0, 1, 1, 1, 2, 2, 2, 3};

// ---------------- helpers ----------------
__device__ __forceinline__ uint32_t to_tf32(float f) {
    uint32_t r;
    asm("cvt.rna.tf32.f32 %0, %1;" : "=r"(r) : "f"(f));
    return r;
}
__device__ __forceinline__ uint32_t smem_u32(const void* p) {
    uint32_t r;
    asm("{ .reg .u64 t; cvta.to.shared.u64 t, %1; cvt.u32.u64 %0, t; }" : "=r"(r) : "l"(p));
    return r;
}
__device__ __forceinline__ void cp16(uint32_t sdst, const void* gsrc) {
    asm volatile("cp.async.cg.shared.global [%0], [%1], 16;" :: "r"(sdst), "l"(gsrc));
}
__device__ __forceinline__ void cp_commit() { asm volatile("cp.async.commit_group;"); }
template <int N> __device__ __forceinline__ void cp_wait() {
    asm volatile("cp.async.wait_group %0;" :: "n"(N));
}
__device__ __forceinline__ void mma_tf32(float* c, const uint32_t* a, const uint32_t* b) {
    asm volatile(
        "mma.sync.aligned.m16n8k8.row.col.f32.tf32.tf32.f32 "
        "{%0,%1,%2,%3}, {%4,%5,%6,%7}, {%8,%9}, {%0,%1,%2,%3};"
        : "+f"(c[0]), "+f"(c[1]), "+f"(c[2]), "+f"(c[3])
        : "r"(a[0]), "r"(a[1]), "r"(a[2]), "r"(a[3]), "r"(b[0]), "r"(b[1]));
}

// ---------------------------------------------------------------------------
// B pack (+ folded prep): pid -> [g][nt][c][s][n8l][ks][lane] uint2 slot
// First 16384 threads also build Wc (sign * path weight) and sig.
// ---------------------------------------------------------------------------
__global__ void __launch_bounds__(256) sgp_wprep(const float* __restrict__ wL,
                                                 const float* __restrict__ wR,
                                                 const float* __restrict__ w_gp,
                                                 const float* __restrict__ a_norm) {
    int pid = blockIdx.x * 256 + threadIdx.x;   // 0 .. 262143
    {
        int lane = pid & 31;
        int ks   = (pid >> 5) & 3;
        int n8l  = (pid >> 7) & 7;
        int s    = (pid >> 10) & 1;
        int c    = (pid >> 11) & 7;
        int nt   = (pid >> 14) & 3;
        int g    = (pid >> 16) & 3;
        int gq = lane >> 2, t4 = lane & 3;
        int n = nt * 64 + n8l * 8 + gq;
        int k = c * 32 + ks * 8 + t4;
        const float* w = s ? wR : wL;
        uint32_t v0 = to_tf32(w[((size_t)n * 256 + k) * 4 + g]);
        uint32_t v1 = to_tf32(w[((size_t)n * 256 + k + 4) * 4 + g]);
        ((uint2*)g_wt)[pid] = make_uint2(v0, v1);
    }
    if (pid < FDIM * 64) {
        int n = pid >> 6;
        int t = pid & 63;
        int i = t >> 3, k = t & 7;
        int mi = c_masks[i], mk = c_masks[k];
        int gi = __popc(mi), gj = __popc(mi ^ mk), gk = __popc(mk);
        int p = c_plut[gi * 16 + gj * 4 + gk];
        int s = 0, aa = mi >> 1;
        while (aa) { s += __popc(aa & mk); aa >>= 1; }
        float sgn = (s & 1) ? -1.0f : 1.0f;
        g_Wc[n * 64 + t] = sgn * w_gp[n * NPATH + p];
        if (t < 4) g_sig[n * 4 + t] = 1.0f / (1.0f + expf(-a_norm[n * 4 + t]));
    }
}

// ---------------------------------------------------------------------------
// A pack/transpose (unchanged, validated)
// ---------------------------------------------------------------------------
__global__ void __launch_bounds__(256) sgp_xt(const float* __restrict__ x) {
    int btile = blockIdx.x >> 3, chunk = blockIdx.x & 7;
    int t = threadIdx.x;
    int lane = t & 31, m16 = t >> 5;
    int gq = lane >> 2, t4 = lane & 3;
    int b0 = btile * 128 + m16 * 16 + gq;
    int k0 = chunk * 32 + t4;
#pragma unroll
    for (int ks = 0; ks < 4; ks++) {
        int kk = k0 + ks * 8;
        float p00[8], p10[8], p01[8], p11[8];
        {
            const float4* q;
            q = (const float4*)(x + ((size_t)b0 * 256 + kk) * 8);
            *(float4*)&p00[0] = q[0]; *(float4*)&p00[4] = q[1];
            q = (const float4*)(x + ((size_t)(b0 + 8) * 256 + kk) * 8);
            *(float4*)&p10[0] = q[0]; *(float4*)&p10[4] = q[1];
            q = (const float4*)(x + ((size_t)b0 * 256 + kk + 4) * 8);
            *(float4*)&p01[0] = q[0]; *(float4*)&p01[4] = q[1];
            q = (const float4*)(x + ((size_t)(b0 + 8) * 256 + kk + 4) * 8);
            *(float4*)&p11[0] = q[0]; *(float4*)&p11[4] = q[1];
        }
#pragma unroll
        for (int plane = 0; plane < 8; plane++) {
            uint4 v = make_uint4(to_tf32(p00[plane]), to_tf32(p10[plane]),
                                 to_tf32(p01[plane]), to_tf32(p11[plane]));
            float* dst = g_xt + (((size_t)(plane * 64 + btile) * 8 + chunk) * 4096)
                              + ((ks * 8 + m16) * 32 + lane) * 4;
            *(uint4*)dst = v;
        }
    }
}

// ---------------------------------------------------------------------------
// tf32 mma.sync GEMM (unchanged, fp16 output)
// ---------------------------------------------------------------------------
__global__ void __launch_bounds__(256, 2)
sgp_gemm() {
    extern __shared__ __align__(16) char sm[];

    const int tid = threadIdx.x;
    const int lane = tid & 31;
    const int wid = tid >> 5;
    const int gq = lane >> 2;
    const int t4 = lane & 3;
    const int wm = wid >> 2;
    const int wn = wid & 3;

    const int nt = blockIdx.x;
    const int n0 = nt * GBN;
    const int rt = blockIdx.y;
    const int plane = rt >> 6;
    const int btile = rt & 63;
    const int grade = c_grade_of_plane[plane];

    const float* Abase = g_xt + ((size_t)(plane * 64 + btile) * 8) * 4096;
    const float* Bbase = g_wt + ((size_t)(grade * 4 + nt) * 8) * 4096;
    const uint32_t smb = smem_u32(sm);

    float acc[4][2][2][4];
#pragma unroll
    for (int mt = 0; mt < 4; mt++)
#pragma unroll
        for (int nn = 0; nn < 2; nn++)
#pragma unroll
            for (int s = 0; s < 2; s++)
#pragma unroll
                for (int r = 0; r < 4; r++) acc[mt][nn][s][r] = 0.0f;

    auto issue = [&](int c, int buf) {
        uint32_t sb = smb + buf * STAGE_B;
        const float* ga = Abase + (size_t)c * 4096;
        const float* gb = Bbase + (size_t)c * 4096;
#pragma unroll
        for (int q = 0; q < 4; q++) {
            int f = q * 256 + tid;
            cp16(sb + f * 16, ga + f * 4);
            cp16(sb + A_STAGE_B + f * 16, gb + f * 4);
        }
        cp_commit();
    };

    issue(0, 0);
    issue(1, 1);

    for (int c = 0; c < NCHUNK; c++) {
        const int buf = c % 3;
        if (c < NCHUNK - 1) cp_wait<1>(); else cp_wait<0>();
        __syncthreads();

        const uint32_t* As = (const uint32_t*)(sm + buf * STAGE_B);
        const uint32_t* Bs = (const uint32_t*)(sm + buf * STAGE_B + A_STAGE_B);

#pragma unroll
        for (int ks = 0; ks < 4; ks++) {
            uint32_t a[4][4];
#pragma unroll
            for (int mt = 0; mt < 4; mt++) {
                const uint4 v = *(const uint4*)(As + ((ks * 8 + wm * 4 + mt) * 32 + lane) * 4);
                a[mt][0] = v.x; a[mt][1] = v.y; a[mt][2] = v.z; a[mt][3] = v.w;
            }
            uint32_t b[2][2][2];
#pragma unroll
            for (int s = 0; s < 2; s++)
#pragma unroll
                for (int nn = 0; nn < 2; nn++) {
                    const uint2 v = *(const uint2*)(Bs +
                        ((s * 8 + wn * 2 + nn) * 4 + ks) * 64 + lane * 2);
                    b[s][nn][0] = v.x; b[s][nn][1] = v.y;
                }
#pragma unroll
            for (int mt = 0; mt < 4; mt++)
#pragma unroll
                for (int nn = 0; nn < 2; nn++)
#pragma unroll
                    for (int s = 0; s < 2; s++)
                        mma_tf32(acc[mt][nn][s], a[mt], b[s][nn]);
        }
        if (c + 2 < NCHUNK) issue(c + 2, (c + 2) % 3);
    }

    const int rbase = plane * 8192 + btile * 128;
#pragma unroll
    for (int s = 0; s < 2; s++) {
        __half* Ob = s ? g_Rh : g_Lh;
#pragma unroll
        for (int mt = 0; mt < 4; mt++) {
#pragma unroll
            for (int nn = 0; nn < 2; nn++) {
                int row = rbase + wm * 64 + mt * 16 + gq;
                int col = n0 + wn * 16 + nn * 8 + 2 * t4;
                Ob[(size_t)col * NROWS + row]           = __float2half_rn(acc[mt][nn][s][0]);
                Ob[(size_t)(col + 1) * NROWS + row]     = __float2half_rn(acc[mt][nn][s][1]);
                Ob[(size_t)col * NROWS + row + 8]       = __float2half_rn(acc[mt][nn][s][2]);
                Ob[(size_t)(col + 1) * NROWS + row + 8] = __float2half_rn(acc[mt][nn][s][3]);
            }
        }
    }
}

// ---------------------------------------------------------------------------
// epilogue v4: block = 8 n x 32 b, 1 point per thread (low reg pressure),
// L load deferred until after the gp loop. x/out staged via padded smem tile
// (coalesced 256B-per-b runs); Wc/sig/bias in smem.
// ---------------------------------------------------------------------------
#define TPR 68   // tile pitch in floats
__global__ void __launch_bounds__(256, 4) sgp_epi(const float* __restrict__ x,
                                                  const float* __restrict__ bL,
                                                  float* __restrict__ out) {
    __shared__ float sWc[8][64];
    __shared__ float sSig[8][4];
    __shared__ float sBias[8];
    __shared__ float sTile[32][TPR];   // 32 b x (8n * 8blade), padded

    const int tid = threadIdx.x;
    const int nblk = blockIdx.x & 31;
    const int bblk = blockIdx.x >> 5;
    const int n0 = nblk * 8;
    const int b0 = bblk * 32;

#pragma unroll
    for (int q = 0; q < 2; q++) {
        int f = q * 256 + tid;            // 0..511
        sWc[f >> 6][f & 63] = g_Wc[(n0 + (f >> 6)) * 64 + (f & 63)];
    }
    if (tid < 32) sSig[tid >> 2][tid & 3] = g_sig[(n0 + (tid >> 2)) * 4 + (tid & 3)];
    if (tid < 8) sBias[tid] = bL[n0 + tid];

    // stage x tile: per b, 8n*8blade = 256B contiguous; 512 float4 coalesced
#pragma unroll
    for (int q = 0; q < 2; q++) {
        int f = q * 256 + tid;            // 0..511
        int bl = f >> 4, c = f & 15;
        float4 v = *(const float4*)(x + (size_t)(b0 + bl) * 2048 + n0 * 8 + c * 4);
        *(float4*)&sTile[bl][c * 4] = v;
    }
    __syncthreads();

    const int wid = tid >> 5;
    const int lane = tid & 31;
    const int n = n0 + wid;
    const int b = b0 + lane;

    // R first; L deferred to shrink peak live registers
    float Rv[8];
#pragma unroll
    for (int i = 0; i < 8; i++)
        Rv[i] = __half2float(g_Rh[(size_t)n * NROWS + i * BDIM + b]);

    float xr[8];
    {
        float qs[4];
        qs[0] = Rv[0] * Rv[0];
        qs[1] = Rv[1] * Rv[1] + Rv[2] * Rv[2] + Rv[3] * Rv[3];
        qs[2] = Rv[4] * Rv[4] + Rv[5] * Rv[5] + Rv[6] * Rv[6];
        qs[3] = Rv[7] * Rv[7];
        float inv[4];
#pragma unroll
        for (int g = 0; g < 4; g++) {
            float nm = sqrtf(sqrtf(qs[g] * qs[g] + 1e-16f));
            inv[g] = 1.0f / (sSig[wid][g] * (nm - 1.0f) + 1.0f + 1e-6f);
        }
        xr[0] = Rv[0] * inv[0];
        xr[1] = Rv[1] * inv[1];  xr[2] = Rv[2] * inv[1];  xr[3] = Rv[3] * inv[1];
        xr[4] = Rv[4] * inv[2];  xr[5] = Rv[5] * inv[2];  xr[6] = Rv[6] * inv[2];
        xr[7] = Rv[7] * inv[3];
    }

    float xv[8];
    {
        float4 a0 = *(const float4*)&sTile[lane][wid * 8 + 0];
        float4 a1 = *(const float4*)&sTile[lane][wid * 8 + 4];
        xv[0] = a0.x; xv[1] = a0.y; xv[2] = a0.z; xv[3] = a0.w;
        xv[4] = a1.x; xv[5] = a1.y; xv[6] = a1.z; xv[7] = a1.w;
    }

    const int JT[64] = {
        0,1,2,3,4,5,6,7,
        1,0,4,5,2,3,7,6,
        2,4,0,6,1,7,3,5,
        3,5,6,0,7,1,2,4,
        4,2,1,7,0,6,5,3,
        5,3,7,1,6,0,4,2,
        6,7,3,2,5,4,0,1,
        7,6,5,4,3,2,1,0 };

    float gp[8] = {0, 0, 0, 0, 0, 0, 0, 0};
#pragma unroll
    for (int i = 0; i < 8; i++) {
#pragma unroll
        for (int k = 0; k < 8; k++)
            gp[JT[i * 8 + k]] += sWc[wid][i * 8 + k] * xv[i] * xr[k];
    }

    const float RS2 = 0.7071067811865476f;
    float o[8];
#pragma unroll
    for (int i = 0; i < 8; i++) {
        float Lv = __half2float(g_Lh[(size_t)n * NROWS + i * BDIM + b]);
        o[i] = (Lv + gp[i]) * RS2;
    }
    o[0] += sBias[wid] * RS2;

    __syncthreads();   // all sTile(x) reads done before overwrite
    *(float4*)&sTile[lane][wid * 8 + 0] = make_float4(o[0], o[1], o[2], o[3]);
    *(float4*)&sTile[lane][wid * 8 + 4] = make_float4(o[4], o[5], o[6], o[7]);
    __syncthreads();

    // cooperative store: per b, 256B contiguous
#pragma unroll
    for (int q = 0; q < 2; q++) {
        int f = q * 256 + tid;            // 0..511
        int bl = f >> 4, c = f & 15;
        *(float4*)(out + (size_t)(b0 + bl) * 2048 + n0 * 8 + c * 4) =
            *(const float4*)&sTile[bl][c * 4];
    }
}

// ---------------------------------------------------------------------------
// inputs: x, w_left, b_left, w_right, a_norm, w_gp
// ---------------------------------------------------------------------------
extern "C" void kernel_launch(void* const* d_in, const int* in_sizes, int n_in,
                              void* d_out, int out_size) {
    const float* x      = (const float*)d_in[0];
    const float* wL     = (const float*)d_in[1];
    const float* bLp    = (const float*)d_in[2];
    const float* wR     = (const float*)d_in[3];
    const float* a_norm = (const float*)d_in[4];
    const float* w_gp   = (const float*)d_in[5];
    float* out = (float*)d_out;

    sgp_wprep<<<1024, 256>>>(wL, wR, w_gp, a_norm);   // B frags + Wc + sig
    sgp_xt<<<512, 256>>>(x);

    cudaFuncSetAttribute(sgp_gemm, cudaFuncAttributeMaxDynamicSharedMemorySize,
                         SMEM_TOTAL);
    dim3 gg(4, 512);
    sgp_gemm<<<gg, 256, SMEM_TOTAL>>>();

    // 32 n-blocks x 256 b-blocks = 8192 blocks of (8 n x 32 b)
    sgp_epi<<<8192, 256>>>(x, bLp, out);
}

// round 13
// speedup vs baseline: 1.9232x; 1.9232x over previous
#include <cuda_runtime.h>
#include <cuda_fp16.h>
#include <cstdint>
#include <math.h>

#define FDIM 256
#define NB 8
#define NPATH 20
#define BDIM 8192
#define NROWS (NB * BDIM)          // 65536 GEMM rows (plane-major)
#define NCHUNK 8                   // K chunks of 32
#define GBN 64                     // n per CTA (per side; both sides computed)

// smem: per stage A 8KB + B 8KB; 3 stages
#define A_STAGE_B 8192
#define STAGE_B 16384
#define SMEM_TOTAL (3 * STAGE_B)   // 49152

// ---------------- scratch (device globals) ----------------
// A fp16 fragment-packed: [plane 8][btile 64][chunk 8][kstep 2][m16 8][lane 32][4 regs]
__device__ uint4 g_xth[(size_t)8 * 64 * 8 * 512];          // 32MB (512 uint4/chunk)
// B fp16 fragment-packed: [g 4][nt 4][chunk 8][s 2][n8l 8][kstep 2][lane 32][uint2]
__device__ uint2 g_wth[(size_t)4 * 4 * 8 * 1024];          // 1MB
__device__ __half g_Lh[(size_t)FDIM * NROWS];              // 32MB [n][row]
__device__ __half g_Rh[(size_t)FDIM * NROWS];              // 32MB [n][row]
__device__ float g_Wc[FDIM * 64];
__device__ float g_sig[FDIM * 4];

__constant__ int c_masks[8] = {0, 1, 2, 4, 3, 5, 6, 7};
__constant__ int c_plut[64] = {
     0, -1, -1, -1,   -1,  1, -1, -1,   -1, -1,  2, -1,   -1, -1, -1,  3,
    -1,  4, -1, -1,    5, -1,  6, -1,   -1,  7, -1,  8,   -1, -1,  9, -1,
    -1, -1, 10, -1,   -1, 11, -1, 12,   13, -1, 14, -1,   -1, 15, -1, -1,
    -1, -1, -1, 16,   -1, -1, 17, -1,   -1, 18, -1, -1,   19, -1, -1, -1
};
__constant__ int c_grade_of_plane[8] = {0, 1, 1, 1, 2, 2, 2, 3};

// ---------------- helpers ----------------
__device__ __forceinline__ uint32_t pack_h2(float lo, float hi) {
    uint32_t r;   // low 16 bits = lo (smaller k index)
    asm("cvt.rn.f16x2.f32 %0, %1, %2;" : "=r"(r) : "f"(hi), "f"(lo));
    return r;
}
__device__ __forceinline__ uint32_t smem_u32(const void* p) {
    uint32_t r;
    asm("{ .reg .u64 t; cvta.to.shared.u64 t, %1; cvt.u32.u64 %0, t; }" : "=r"(r) : "l"(p));
    return r;
}
__device__ __forceinline__ void cp16(uint32_t sdst, const void* gsrc) {
    asm volatile("cp.async.cg.shared.global [%0], [%1], 16;" :: "r"(sdst), "l"(gsrc));
}
__device__ __forceinline__ void cp_commit() { asm volatile("cp.async.commit_group;"); }
template <int N> __device__ __forceinline__ void cp_wait() {
    asm volatile("cp.async.wait_group %0;" :: "n"(N));
}
__device__ __forceinline__ void mma_f16(float* c, const uint32_t* a, const uint32_t* b) {
    asm volatile(
        "mma.sync.aligned.m16n8k16.row.col.f32.f16.f16.f32 "
        "{%0,%1,%2,%3}, {%4,%5,%6,%7}, {%8,%9}, {%0,%1,%2,%3};"
        : "+f"(c[0]), "+f"(c[1]), "+f"(c[2]), "+f"(c[3])
        : "r"(a[0]), "r"(a[1]), "r"(a[2]), "r"(a[3]), "r"(b[0]), "r"(b[1]));
}

// ---------------------------------------------------------------------------
// B pack (+ folded prep): pid -> [g][nt][c][s][n8l][kstep][lane] uint2 slot
//   b0 = {w[n][k0+2t4][g], w[n][k0+2t4+1][g]}, b1 = same at k0+8
// First 16384 threads also build Wc and sig.
// ---------------------------------------------------------------------------
__global__ void __launch_bounds__(256) sgp_wprep(const float* __restrict__ wL,
                                                 const float* __restrict__ wR,
                                                 const float* __restrict__ w_gp,
                                                 const float* __restrict__ a_norm) {
    int pid = blockIdx.x * 256 + threadIdx.x;   // 0 .. 131071
    {
        int lane  = pid & 31;
        int kstep = (pid >> 5) & 1;
        int n8l   = (pid >> 6) & 7;
        int s     = (pid >> 9) & 1;
        int c     = (pid >> 10) & 7;
        int nt    = (pid >> 13) & 3;
        int g     = (pid >> 15) & 3;
        int gq = lane >> 2, t4 = lane & 3;
        int n = nt * 64 + n8l * 8 + gq;
        int k0 = c * 32 + kstep * 16 + 2 * t4;
        const float* w = s ? wR : wL;
        uint32_t b0 = pack_h2(w[((size_t)n * 256 + k0) * 4 + g],
                              w[((size_t)n * 256 + k0 + 1) * 4 + g]);
        uint32_t b1 = pack_h2(w[((size_t)n * 256 + k0 + 8) * 4 + g],
                              w[((size_t)n * 256 + k0 + 9) * 4 + g]);
        g_wth[pid] = make_uint2(b0, b1);
    }
    if (pid < FDIM * 64) {
        int n = pid >> 6;
        int t = pid & 63;
        int i = t >> 3, k = t & 7;
        int mi = c_masks[i], mk = c_masks[k];
        int gi = __popc(mi), gj = __popc(mi ^ mk), gk = __popc(mk);
        int p = c_plut[gi * 16 + gj * 4 + gk];
        int s = 0, aa = mi >> 1;
        while (aa) { s += __popc(aa & mk); aa >>= 1; }
        float sgn = (s & 1) ? -1.0f : 1.0f;
        g_Wc[n * 64 + t] = sgn * w_gp[n * NPATH + p];
        if (t < 4) g_sig[n * 4 + t] = 1.0f / (1.0f + expf(-a_norm[n * 4 + t]));
    }
}

// ---------------------------------------------------------------------------
// A pack/transpose -> fp16 fragments. block = (btile 64, chunk 8),
// 256 threads = (m16 8, lane 32); per kstep each thread reads 8 (b,m)
// positions (full 32B sectors) and emits one uint4 per plane (coalesced).
// Fragment regs: r0={row,k0,k0+1} r1={row+8,..} r2={row,k0+8,k0+9} r3={row+8,..}
// ---------------------------------------------------------------------------
__global__ void __launch_bounds__(256) sgp_xt(const float* __restrict__ x) {
    int btile = blockIdx.x >> 3, chunk = blockIdx.x & 7;
    int t = threadIdx.x;
    int lane = t & 31, m16 = t >> 5;
    int gq = lane >> 2, t4 = lane & 3;
    int row0 = btile * 128 + m16 * 16 + gq;
#pragma unroll
    for (int ks = 0; ks < 2; ks++) {
        int k0 = chunk * 32 + ks * 16 + 2 * t4;
        float v[2][4][8];   // [rowhalf][col: k0,k0+1,k0+8,k0+9][plane]
#pragma unroll
        for (int r = 0; r < 2; r++) {
            int b = row0 + r * 8;
            const int cols[4] = {k0, k0 + 1, k0 + 8, k0 + 9};
#pragma unroll
            for (int ci = 0; ci < 4; ci++) {
                const float4* q = (const float4*)(x + ((size_t)b * 256 + cols[ci]) * 8);
                *(float4*)&v[r][ci][0] = q[0];
                *(float4*)&v[r][ci][4] = q[1];
            }
        }
#pragma unroll
        for (int p = 0; p < 8; p++) {
            uint32_t r0 = pack_h2(v[0][0][p], v[0][1][p]);
            uint32_t r1 = pack_h2(v[1][0][p], v[1][1][p]);
            uint32_t r2 = pack_h2(v[0][2][p], v[0][3][p]);
            uint32_t r3 = pack_h2(v[1][2][p], v[1][3][p]);
            size_t idx = ((((size_t)(p * 64 + btile) * 8 + chunk) * 2 + ks) * 8 + m16) * 32 + lane;
            g_xth[idx] = make_uint4(r0, r1, r2, r3);
        }
    }
}

// ---------------------------------------------------------------------------
// fp16 mma.sync GEMM (m16n8k16), fragment-packed smem, 3-stage cp.async.
// CTA: 128 rows (one plane) x 64 n x both sides. 8 warps: wm(2) x wn(4).
// Output fp16 col-major [n][row] into g_Lh / g_Rh (C layout identical to tf32).
// ---------------------------------------------------------------------------
__global__ void __launch_bounds__(256, 2)
sgp_gemm() {
    extern __shared__ __align__(16) char sm[];

    const int tid = threadIdx.x;
    const int lane = tid & 31;
    const int wid = tid >> 5;
    const int gq = lane >> 2;
    const int t4 = lane & 3;
    const int wm = wid >> 2;           // 0..1 -> m offset wm*64
    const int wn = wid & 3;            // 0..3 -> n block of 16

    const int nt = blockIdx.x;         // 0..3 (fastest: A reuse in L2)
    const int n0 = nt * GBN;
    const int rt = blockIdx.y;         // 0..511
    const int plane = rt >> 6;
    const int btile = rt & 63;
    const int grade = c_grade_of_plane[plane];

    const uint4* Abase = g_xth + ((size_t)(plane * 64 + btile) * 8) * 512;
    const uint4* Bbase = (const uint4*)(g_wth + ((size_t)(grade * 4 + nt) * 8) * 1024);
    const uint32_t smb = smem_u32(sm);

    float acc[4][2][2][4];
#pragma unroll
    for (int mt = 0; mt < 4; mt++)
#pragma unroll
        for (int nn = 0; nn < 2; nn++)
#pragma unroll
            for (int s = 0; s < 2; s++)
#pragma unroll
                for (int r = 0; r < 4; r++) acc[mt][nn][s][r] = 0.0f;

    // issue chunk: A 512 uint4 + B 512 uint4; 2+2 cp16 per thread
    auto issue = [&](int c, int buf) {
        uint32_t sb = smb + buf * STAGE_B;
        const uint4* ga = Abase + (size_t)c * 512;
        const uint4* gb = Bbase + (size_t)c * 512;
#pragma unroll
        for (int q = 0; q < 2; q++) {
            int f = q * 256 + tid;
            cp16(sb + f * 16, ga + f);
            cp16(sb + A_STAGE_B + f * 16, gb + f);
        }
        cp_commit();
    };

    issue(0, 0);
    issue(1, 1);

    for (int c = 0; c < NCHUNK; c++) {
        const int buf = c % 3;
        if (c < NCHUNK - 1) cp_wait<1>(); else cp_wait<0>();
        __syncthreads();

        const uint32_t* As = (const uint32_t*)(sm + buf * STAGE_B);
        const uint32_t* Bs = (const uint32_t*)(sm + buf * STAGE_B + A_STAGE_B);

#pragma unroll
        for (int ks = 0; ks < 2; ks++) {
            uint32_t a[4][4];
#pragma unroll
            for (int mt = 0; mt < 4; mt++) {
                const uint4 v = *(const uint4*)(As + ((ks * 8 + wm * 4 + mt) * 32 + lane) * 4);
                a[mt][0] = v.x; a[mt][1] = v.y; a[mt][2] = v.z; a[mt][3] = v.w;
            }
            uint32_t b[2][2][2];   // [s][nn][reg]
#pragma unroll
            for (int s = 0; s < 2; s++)
#pragma unroll
                for (int nn = 0; nn < 2; nn++) {
                    const uint2 v = *(const uint2*)(Bs +
                        (((s * 8 + wn * 2 + nn) * 2 + ks) * 32 + lane) * 2);
                    b[s][nn][0] = v.x; b[s][nn][1] = v.y;
                }
#pragma unroll
            for (int mt = 0; mt < 4; mt++)
#pragma unroll
                for (int nn = 0; nn < 2; nn++)
#pragma unroll
                    for (int s = 0; s < 2; s++)
                        mma_f16(acc[mt][nn][s], a[mt], b[s][nn]);
        }
        if (c + 2 < NCHUNK) issue(c + 2, (c + 2) % 3);
    }

    const int rbase = plane * 8192 + btile * 128;
#pragma unroll
    for (int s = 0; s < 2; s++) {
        __half* Ob = s ? g_Rh : g_Lh;
#pragma unroll
        for (int mt = 0; mt < 4; mt++) {
#pragma unroll
            for (int nn = 0; nn < 2; nn++) {
                int row = rbase + wm * 64 + mt * 16 + gq;
                int col = n0 + wn * 16 + nn * 8 + 2 * t4;
                Ob[(size_t)col * NROWS + row]           = __float2half_rn(acc[mt][nn][s][0]);
                Ob[(size_t)(col + 1) * NROWS + row]     = __float2half_rn(acc[mt][nn][s][1]);
                Ob[(size_t)col * NROWS + row + 8]       = __float2half_rn(acc[mt][nn][s][2]);
                Ob[(size_t)(col + 1) * NROWS + row + 8] = __float2half_rn(acc[mt][nn][s][3]);
            }
        }
    }
}

// ---------------------------------------------------------------------------
// epilogue (R10 version, best measured): block = 8 n x 64 b; warp = fixed n,
// 2 b per thread; Wc/sig/bias in smem; L/R via __half2; direct x/out access.
// ---------------------------------------------------------------------------
__global__ void __launch_bounds__(256) sgp_epi(const float* __restrict__ x,
                                               const float* __restrict__ bL,
                                               float* __restrict__ out) {
    __shared__ float sWc[8][64];
    __shared__ float sSig[8][4];
    __shared__ float sBias[8];

    const int tid = threadIdx.x;
    const int nblk = blockIdx.x & 31;
    const int bblk = blockIdx.x >> 5;
    const int n0 = nblk * 8;
    const int b0 = bblk * 64;

#pragma unroll
    for (int q = 0; q < 2; q++) {
        int f = q * 256 + tid;            // 0..511
        sWc[f >> 6][f & 63] = g_Wc[(n0 + (f >> 6)) * 64 + (f & 63)];
    }
    if (tid < 32) sSig[tid >> 2][tid & 3] = g_sig[(n0 + (tid >> 2)) * 4 + (tid & 3)];
    if (tid < 8) sBias[tid] = bL[n0 + tid];
    __syncthreads();

    const int wid = tid >> 5;
    const int lane = tid & 31;
    const int n = n0 + wid;
    const int b = b0 + lane * 2;          // 2 consecutive b per thread

    float Lv[2][8], Rv[2][8];
#pragma unroll
    for (int i = 0; i < 8; i++) {
        __half2 lh = *(const __half2*)&g_Lh[(size_t)n * NROWS + i * BDIM + b];
        __half2 rh = *(const __half2*)&g_Rh[(size_t)n * NROWS + i * BDIM + b];
        float2 lf = __half22float2(lh);
        float2 rf = __half22float2(rh);
        Lv[0][i] = lf.x; Lv[1][i] = lf.y;
        Rv[0][i] = rf.x; Rv[1][i] = rf.y;
    }

    float xv[2][8];
#pragma unroll
    for (int p = 0; p < 2; p++) {
        const float4* xp = (const float4*)(x + ((size_t)(b + p) * FDIM + n) * NB);
        float4 x0 = xp[0], x1 = xp[1];
        xv[p][0] = x0.x; xv[p][1] = x0.y; xv[p][2] = x0.z; xv[p][3] = x0.w;
        xv[p][4] = x1.x; xv[p][5] = x1.y; xv[p][6] = x1.z; xv[p][7] = x1.w;
    }

    float xr[2][8];
#pragma unroll
    for (int p = 0; p < 2; p++) {
        float qs[4];
        qs[0] = Rv[p][0] * Rv[p][0];
        qs[1] = Rv[p][1] * Rv[p][1] + Rv[p][2] * Rv[p][2] + Rv[p][3] * Rv[p][3];
        qs[2] = Rv[p][4] * Rv[p][4] + Rv[p][5] * Rv[p][5] + Rv[p][6] * Rv[p][6];
        qs[3] = Rv[p][7] * Rv[p][7];
        float inv[4];
#pragma unroll
        for (int g = 0; g < 4; g++) {
            float nm = sqrtf(sqrtf(qs[g] * qs[g] + 1e-16f));
            inv[g] = 1.0f / (sSig[wid][g] * (nm - 1.0f) + 1.0f + 1e-6f);
        }
        xr[p][0] = Rv[p][0] * inv[0];
        xr[p][1] = Rv[p][1] * inv[1];  xr[p][2] = Rv[p][2] * inv[1];  xr[p][3] = Rv[p][3] * inv[1];
        xr[p][4] = Rv[p][4] * inv[2];  xr[p][5] = Rv[p][5] * inv[2];  xr[p][6] = Rv[p][6] * inv[2];
        xr[p][7] = Rv[p][7] * inv[3];
    }

    const int JT[64] = {
        0,1,2,3,4,5,6,7,
        1,0,4,5,2,3,7,6,
        2,4,0,6,1,7,3,5,
        3,5,6,0,7,1,2,4,
        4,2,1,7,0,6,5,3,
        5,3,7,1,6,0,4,2,
        6,7,3,2,5,4,0,1,
        7,6,5,4,3,2,1,0 };

    float gp[2][8] = {{0,0,0,0,0,0,0,0},{0,0,0,0,0,0,0,0}};
#pragma unroll
    for (int i = 0; i < 8; i++) {
#pragma unroll
        for (int k = 0; k < 8; k++) {
            float wcv = sWc[wid][i * 8 + k];      // uniform broadcast LDS
            int j = JT[i * 8 + k];
            gp[0][j] += wcv * xv[0][i] * xr[0][k];
            gp[1][j] += wcv * xv[1][i] * xr[1][k];
        }
    }

    const float RS2 = 0.7071067811865476f;
    const float bias = sBias[wid] * RS2;
#pragma unroll
    for (int p = 0; p < 2; p++) {
        float o[8];
#pragma unroll
        for (int i = 0; i < 8; i++) o[i] = (Lv[p][i] + gp[p][i]) * RS2;
        o[0] += bias;
        float4* op = (float4*)(out + ((size_t)(b + p) * FDIM + n) * NB);
        op[0] = make_float4(o[0], o[1], o[2], o[3]);
        op[1] = make_float4(o[4], o[5], o[6], o[7]);
    }
}

// ---------------------------------------------------------------------------
// inputs: x, w_left, b_left, w_right, a_norm, w_gp
// ---------------------------------------------------------------------------
extern "C" void kernel_launch(void* const* d_in, const int* in_sizes, int n_in,
                              void* d_out, int out_size) {
    const float* x      = (const float*)d_in[0];
    const float* wL     = (const float*)d_in[1];
    const float* bLp    = (const float*)d_in[2];
    const float* wR     = (const float*)d_in[3];
    const float* a_norm = (const float*)d_in[4];
    const float* w_gp   = (const float*)d_in[5];
    float* out = (float*)d_out;

    sgp_wprep<<<512, 256>>>(wL, wR, w_gp, a_norm);   // B fp16 frags + Wc + sig
    sgp_xt<<<512, 256>>>(x);                         // A fp16 frags

    cudaFuncSetAttribute(sgp_gemm, cudaFuncAttributeMaxDynamicSharedMemorySize,
                         SMEM_TOTAL);
    dim3 gg(4, 512);                                 // n-tiles fastest
    sgp_gemm<<<gg, 256, SMEM_TOTAL>>>();

    // 32 n-blocks x 128 b-blocks = 4096 blocks of (8 n x 64 b)
    sgp_epi<<<4096, 256>>>(x, bLp, out);
}